// round 10
// baseline (speedup 1.0000x reference)
#include <cuda_runtime.h>
#include <cuda_fp16.h>
#include <cstdint>

#define B_DIM 512
#define T_DIM 128
#define D_DIM 300
#define DPAD  320
#define H_DIM 1024
#define NCOL  4096
#define NROUND (T_DIM + 2)   // 130

typedef uint32_t u32;

// ------------------------------------------------------------------
// Persistent device buffers
// ------------------------------------------------------------------
__device__ __align__(16) __half g_x[(size_t)B_DIM * T_DIM * DPAD];
__device__ __align__(16) __half g_wih0[(size_t)4 * H_DIM * DPAD];
__device__ __align__(16) __half g_whh0[(size_t)4 * H_DIM * H_DIM];
__device__ __align__(16) __half g_wih1[(size_t)4 * H_DIM * H_DIM];
__device__ __align__(16) __half g_whh1[(size_t)4 * H_DIM * H_DIM];
__device__ __align__(16) __half g_h0b[2][(size_t)B_DIM * H_DIM];
__device__ __align__(16) __half g_h1b[2][(size_t)B_DIM * H_DIM];
__device__ __align__(16) float g_part[2][(size_t)B_DIM * NCOL];
__device__ __align__(16) float g_c0[(size_t)B_DIM * H_DIM];
__device__ __align__(16) float g_c1[(size_t)B_DIM * H_DIM];
__device__ __align__(16) float g_acc[(size_t)B_DIM * H_DIM];
__device__ __align__(16) float g_b0[NCOL];   // INTERLEAVED: g_b0[n] = b[(n&3)*H + (n>>2)]
__device__ __align__(16) float g_b1[NCOL];
__device__ int g_ctr[NROUND];
__device__ int g_sync;

// ------------------------------------------------------------------
// Helpers
// ------------------------------------------------------------------
__device__ __forceinline__ u32 smem_to_u32(const void* p) {
    u32 a;
    asm("{ .reg .u64 t; cvta.to.shared.u64 t, %1; cvt.u32.u64 %0, t; }" : "=r"(a) : "l"(p));
    return a;
}
__device__ __forceinline__ void cp16(u32 s, const void* g) {
    asm volatile("cp.async.cg.shared.global [%0], [%1], 16;" :: "r"(s), "l"(g));
}
__device__ __forceinline__ void mbar_init(u32 mb, u32 cnt) {
    asm volatile("mbarrier.init.shared.b64 [%0], %1;" :: "r"(mb), "r"(cnt) : "memory");
}
__device__ __forceinline__ void mbar_arrive(u32 mb) {
    asm volatile("mbarrier.arrive.shared.b64 _, [%0];" :: "r"(mb) : "memory");
}
__device__ __forceinline__ void cp_arrive_noinc(u32 mb) {
    asm volatile("cp.async.mbarrier.arrive.noinc.shared.b64 [%0];" :: "r"(mb) : "memory");
}
__device__ __forceinline__ void mbar_wait(u32 mb, u32 parity) {
    u32 done;
    asm volatile("{\n\t.reg .pred p;\n\t"
        "mbarrier.try_wait.parity.acquire.cta.shared::cta.b64 p, [%1], %2;\n\t"
        "selp.b32 %0, 1, 0, p;\n\t}" : "=r"(done) : "r"(mb), "r"(parity) : "memory");
    if (!done) {
        asm volatile("{\n\t.reg .pred P1;\n\t"
            "WAIT_LOOP_%=:\n\t"
            "mbarrier.try_wait.parity.acquire.cta.shared::cta.b64 P1, [%0], %1, 0x989680;\n\t"
            "@P1 bra.uni WAIT_DONE_%=;\n\t"
            "bra.uni WAIT_LOOP_%=;\n\t"
            "WAIT_DONE_%=:\n\t}" :: "r"(mb), "r"(parity) : "memory");
    }
}
__device__ __forceinline__ void ldsm4(u32 addr, u32* r) {
    asm volatile("ldmatrix.sync.aligned.m8n8.x4.shared.b16 {%0,%1,%2,%3}, [%4];"
                 : "=r"(r[0]), "=r"(r[1]), "=r"(r[2]), "=r"(r[3]) : "r"(addr));
}
__device__ __forceinline__ void mma_f16(float* d, const u32* a, u32 b0, u32 b1) {
    asm volatile("mma.sync.aligned.m16n8k16.row.col.f32.f16.f16.f32 "
                 "{%0,%1,%2,%3}, {%4,%5,%6,%7}, {%8,%9}, {%0,%1,%2,%3};"
                 : "+f"(d[0]), "+f"(d[1]), "+f"(d[2]), "+f"(d[3])
                 : "r"(a[0]), "r"(a[1]), "r"(a[2]), "r"(a[3]), "r"(b0), "r"(b1));
}
__device__ __forceinline__ u32 swz(u32 row, u32 q) {
    return row * 128u + ((q ^ (row & 7u)) << 4);
}
__device__ __forceinline__ float sigf(float x) { return __fdividef(1.0f, 1.0f + __expf(-x)); }
__device__ __forceinline__ float tanhf_(float x) {
    return 1.0f - 2.0f * __fdividef(1.0f, 1.0f + __expf(2.0f * x));
}

#define TILE_B   16384
#define BUF_B    (2 * TILE_B)
#define SMEM_TOT (1024 + 3 * BUF_B)  // 99328 -> 2 CTAs/SM

// ------------------------------------------------------------------
// Persistent kernel: 130 device-side rounds with work stealing.
// Round r jobs (long first): L0[r] (r<=127, 21ch), L1B[r-2] (r>=2, 16ch),
// L1A[r-1] (1<=r<=128, 16ch). Tile 128x128, 8 warps (2Mx4N), BK=64.
// ------------------------------------------------------------------
__global__ void __launch_bounds__(256, 2)
lstm_persist(int ncta) {
    extern __shared__ __align__(16) char smem[];
    const u32 sbase = smem_to_u32(smem);
    const u32 sb = sbase + 1024;
    volatile int* s_job = (volatile int*)(smem + 128);
    const int tid = threadIdx.x;
    const int lane = tid & 31;
    const int wid = tid >> 5;
    const int wm = wid >> 2;
    const int wn = wid & 3;

    if (tid == 0) {
#pragma unroll
        for (int s = 0; s < 3; s++) {
            mbar_init(sbase + 32 + s * 8, 256);  // full
            mbar_init(sbase + 64 + s * 8, 256);  // empty
        }
    }
    __syncthreads();

    const int r_ = tid >> 1;
    const int h4 = (tid & 1) * 4;

    int cbase = 0;  // absolute chunk counter (ring phase carries across jobs)

    for (int rnd = 0; rnd < NROUND; ++rnd) {
        const int n0  = (rnd <= T_DIM - 1) ? 128 : 0;
        const int n1b = (rnd >= 2) ? 128 : 0;
        const int n1a = (rnd >= 1 && rnd <= T_DIM) ? 128 : 0;
        const int njobs = n0 + n1b + n1a;

        for (;;) {
            if (tid == 0) *s_job = atomicAdd(&g_ctr[rnd], 1);
            __syncthreads();
            const int j = *s_job;
            __syncthreads();
            if (j >= njobs) break;

            int type, step, jb;
            if (j < n0)            { type = 2; step = rnd;     jb = j; }
            else if (j < n0 + n1b) { type = 0; step = rnd - 2; jb = j - n0; }
            else                   { type = 1; step = rnd - 1; jb = j - n0 - n1b; }
            const int u0 = (jb & 31) * 32;
            const int m0 = (jb >> 5) * 128;
            const int wrow = (r_ & 3) * H_DIM + u0 + (r_ >> 2);

            const __half *pa0, *pw0, *pa1 = nullptr, *pw1 = nullptr;
            int nc0, NC;
            if (type == 2) {
                pa0 = g_x + (size_t)(m0 + r_) * (T_DIM * DPAD) + (size_t)step * DPAD;
                pw0 = g_wih0 + (size_t)wrow * DPAD;
                nc0 = DPAD / 64;
                pa1 = g_h0b[(step - 1) & 1] + (size_t)(m0 + r_) * H_DIM;
                pw1 = g_whh0 + (size_t)wrow * H_DIM;
                NC = nc0 + 16;
            } else if (type == 1) {
                pa0 = g_h0b[step & 1] + (size_t)(m0 + r_) * H_DIM;
                pw0 = g_wih1 + (size_t)wrow * H_DIM;
                nc0 = 16; NC = 16;
            } else {
                pa0 = g_h1b[(step - 1) & 1] + (size_t)(m0 + r_) * H_DIM;
                pw0 = g_whh1 + (size_t)wrow * H_DIM;
                nc0 = 16; NC = 16;
            }

            float acc[4][4][4];
#pragma unroll
            for (int mi = 0; mi < 4; mi++)
#pragma unroll
                for (int nf = 0; nf < 4; nf++)
#pragma unroll
                    for (int q = 0; q < 4; q++) acc[mi][nf][q] = 0.0f;

            auto produce = [&](int q_abs) {
                const int c = q_abs - cbase;
                if (q_abs >= 3)
                    mbar_wait(sbase + 64 + (u32)(q_abs % 3) * 8,
                              (u32)(((q_abs / 3) - 1) & 1));
                const __half* pa; const __half* pw; int k0;
                if (c < nc0) { pa = pa0; pw = pw0; k0 = c * 64; }
                else         { pa = pa1; pw = pw1; k0 = (c - nc0) * 64; }
                const u32 d = sb + (u32)(q_abs % 3) * BUF_B;
#pragma unroll
                for (int jj = 0; jj < 4; jj++) {
                    const int q = h4 + jj;
                    const u32 so = swz((u32)r_, (u32)q);
                    const int e = k0 + q * 8;
                    cp16(d + so, pa + e);
                    cp16(d + TILE_B + so, pw + e);
                }
                cp_arrive_noinc(sbase + 32 + (u32)(q_abs % 3) * 8);
            };

            int prod = cbase;
            const int cend = cbase + NC;
            for (int a = cbase; a < cend; a++) {
                while (prod < cend && prod <= a + 2) { produce(prod); prod++; }
                mbar_wait(sbase + 32 + (u32)(a % 3) * 8, (u32)((a / 3) & 1));

                const u32 bA = sb + (u32)(a % 3) * BUF_B;
                const u32 bW = bA + TILE_B;
#pragma unroll
                for (int kk = 0; kk < 4; kk++) {
                    u32 av[4][4], wv[2][4];
                    const u32 aq = 2 * kk + (lane >> 4);
#pragma unroll
                    for (int mi = 0; mi < 4; mi++) {
                        const u32 row = wm * 64 + mi * 16 + (lane & 15);
                        ldsm4(bA + swz(row, aq), av[mi]);
                    }
                    const u32 wq = 2 * kk + ((lane >> 3) & 1);
#pragma unroll
                    for (int nf2 = 0; nf2 < 2; nf2++) {
                        const u32 row = wn * 32 + nf2 * 16 + (lane & 7) + ((lane >> 4) << 3);
                        ldsm4(bW + swz(row, wq), wv[nf2]);
                    }
#pragma unroll
                    for (int mi = 0; mi < 4; mi++)
#pragma unroll
                        for (int nf = 0; nf < 4; nf++) {
                            const u32* W = wv[nf >> 1] + (nf & 1) * 2;
                            mma_f16(acc[mi][nf], av[mi], W[0], W[1]);
                        }
                }
                mbar_arrive(sbase + 64 + (u32)(a % 3) * 8);
            }
            cbase = cend;

            // ---------------- epilogue ----------------
            if (type == 1) {
                float* outp = g_part[step & 1];
#pragma unroll
                for (int mi = 0; mi < 4; mi++)
#pragma unroll
                    for (int nf = 0; nf < 4; nf++) {
                        const int row0 = m0 + wm * 64 + mi * 16 + (lane >> 2);
                        const int col = u0 * 4 + wn * 32 + nf * 8 + 2 * (lane & 3);
                        *(float2*)(outp + (size_t)row0 * NCOL + col) =
                            make_float2(acc[mi][nf][0], acc[mi][nf][1]);
                        *(float2*)(outp + (size_t)(row0 + 8) * NCOL + col) =
                            make_float2(acc[mi][nf][2], acc[mi][nf][3]);
                    }
            } else {
                float* cmem = (type == 0) ? g_c1 : g_c0;
                __half* hout = (type == 0) ? g_h1b[step & 1] : g_h0b[step & 1];
                const float* extra = (type == 0) ? g_part[step & 1] : nullptr;
                const float* gb = (type == 0) ? g_b1 : g_b0;
                const bool owner = ((lane & 1) == 0);
                const int cc = 2 * (lane & 3);
#pragma unroll
                for (int mi = 0; mi < 4; mi++)
#pragma unroll
                    for (int nf = 0; nf < 4; nf++) {
                        float v0 = acc[mi][nf][0], v1 = acc[mi][nf][1];
                        float v2 = acc[mi][nf][2], v3 = acc[mi][nf][3];
                        const float p0 = __shfl_xor_sync(0xffffffffu, v0, 1);
                        const float p1 = __shfl_xor_sync(0xffffffffu, v1, 1);
                        const float p2 = __shfl_xor_sync(0xffffffffu, v2, 1);
                        const float p3 = __shfl_xor_sync(0xffffffffu, v3, 1);
                        if (owner) {
                            const int nl = wn * 32 + nf * 8 + cc;
                            const int ucol = u0 + (nl >> 2);
                            // g_b* are pre-interleaved: gb[u0*4+nl+g] = b[g*H + ucol]
                            const float4 bv = *(const float4*)(gb + u0 * 4 + nl);
                            const int rowa = m0 + wm * 64 + mi * 16 + (lane >> 2);
#pragma unroll
                            for (int rh = 0; rh < 2; rh++) {
                                const int b = rowa + rh * 8;
                                float iv = (rh ? v2 : v0) + bv.x;
                                float fv = (rh ? v3 : v1) + bv.y;
                                float gv = (rh ? p2 : p0) + bv.z;
                                float ov = (rh ? p3 : p1) + bv.w;
                                if (extra) {
                                    const float2 e01 = __ldcg((const float2*)(extra + (size_t)b * NCOL + u0 * 4 + nl));
                                    const float2 e23 = __ldcg((const float2*)(extra + (size_t)b * NCOL + u0 * 4 + nl + 2));
                                    iv += e01.x; fv += e01.y; gv += e23.x; ov += e23.y;
                                }
                                const size_t ci = (size_t)b * H_DIM + ucol;
                                const float cold = __ldcg(cmem + ci);
                                const float cn = sigf(fv) * cold + sigf(iv) * tanhf_(gv);
                                const float hn = sigf(ov) * tanhf_(cn);
                                cmem[ci] = cn;
                                hout[ci] = __float2half(hn);
                                if (type == 0) g_acc[ci] = __ldcg(g_acc + ci) + hn;
                            }
                        }
                    }
            }
            __syncthreads();
        }

        // ---------------- grid-wide barrier ----------------
        __threadfence();
        __syncthreads();
        if (tid == 0) {
            atomicAdd(&g_sync, 1);
            const int target = ncta * (rnd + 1);
            while (*(volatile int*)&g_sync < target) { __nanosleep(64); }
            __threadfence();
        }
        __syncthreads();
    }
}

// ------------------------------------------------------------------
__global__ void prolog_k(const float* __restrict__ x,
                         const float* __restrict__ Wih0, const float* __restrict__ Whh0,
                         const float* __restrict__ Wih1, const float* __restrict__ Whh1,
                         const float* __restrict__ bih0, const float* __restrict__ bhh0,
                         const float* __restrict__ bih1, const float* __restrict__ bhh1) {
    const size_t stride = (size_t)gridDim.x * blockDim.x;
    const size_t tid0 = (size_t)blockIdx.x * blockDim.x + threadIdx.x;
    if (tid0 == 0) g_sync = 0;
    for (size_t i = tid0; i < NROUND; i += stride) g_ctr[i] = 0;
    // interleaved bias: g_b[n] = b[(n&3)*H + (n>>2)]  (col n = gate n&3 of unit n>>2)
    for (size_t i = tid0; i < NCOL; i += stride) {
        const size_t src = (i & 3) * H_DIM + (i >> 2);
        g_b0[i] = bih0[src] + bhh0[src];
        g_b1[i] = bih1[src] + bhh1[src];
    }
    {
        const size_t n = (size_t)4 * H_DIM * DPAD;
        for (size_t i = tid0; i < n; i += stride) {
            const size_t row = i / DPAD;
            const int k = (int)(i % DPAD);
            g_wih0[i] = __float2half((k < D_DIM) ? Wih0[row * D_DIM + k] : 0.0f);
        }
    }
    {
        const size_t n = (size_t)4 * H_DIM * H_DIM;
        for (size_t i = tid0; i < n; i += stride) {
            g_whh0[i] = __float2half(Whh0[i]);
            g_wih1[i] = __float2half(Wih1[i]);
            g_whh1[i] = __float2half(Whh1[i]);
        }
    }
    {
        const size_t n = (size_t)B_DIM * T_DIM * DPAD;
        for (size_t i = tid0; i < n; i += stride) {
            const size_t bt = i / DPAD;
            const int k = (int)(i % DPAD);
            g_x[i] = __float2half((k < D_DIM) ? x[bt * D_DIM + k] : 0.0f);
        }
    }
    {
        const size_t n = (size_t)B_DIM * H_DIM;
        for (size_t i = tid0; i < n; i += stride) {
            g_h0b[0][i] = __float2half(0.0f);
            g_h0b[1][i] = __float2half(0.0f);
            g_h1b[0][i] = __float2half(0.0f);
            g_h1b[1][i] = __float2half(0.0f);
            g_c0[i] = 0.0f; g_c1[i] = 0.0f; g_acc[i] = 0.0f;
        }
    }
}

__global__ void finalize_k(const float* __restrict__ Wdec,
                           const float* __restrict__ bdec, float* __restrict__ out) {
    const int b = blockIdx.x;
    const int tid = threadIdx.x;  // 128
    float p = 0.0f;
    for (int u = tid; u < H_DIM; u += 128)
        p += g_acc[(size_t)b * H_DIM + u] * Wdec[u];
#pragma unroll
    for (int o = 16; o; o >>= 1) p += __shfl_down_sync(0xffffffffu, p, o);
    __shared__ float red[4];
    if ((tid & 31) == 0) red[tid >> 5] = p;
    __syncthreads();
    if (tid == 0)
        out[b] = (red[0] + red[1] + red[2] + red[3]) * (1.0f / (float)T_DIM) + bdec[0];
}

// ------------------------------------------------------------------
extern "C" void kernel_launch(void* const* d_in, const int* in_sizes, int n_in,
                              void* d_out, int out_size) {
    const float* x    = (const float*)d_in[0];
    const float* Wih0 = (const float*)d_in[1];
    const float* Whh0 = (const float*)d_in[2];
    const float* bih0 = (const float*)d_in[3];
    const float* bhh0 = (const float*)d_in[4];
    const float* Wih1 = (const float*)d_in[5];
    const float* Whh1 = (const float*)d_in[6];
    const float* bih1 = (const float*)d_in[7];
    const float* bhh1 = (const float*)d_in[8];
    const float* Wdec = (const float*)d_in[9];
    const float* bdec = (const float*)d_in[10];
    float* out = (float*)d_out;

    cudaFuncSetAttribute(lstm_persist, cudaFuncAttributeMaxDynamicSharedMemorySize, SMEM_TOT);

    int nsm = 0;
    cudaDeviceGetAttribute(&nsm, cudaDevAttrMultiProcessorCount, 0);
    int per_sm = 0;
    cudaOccupancyMaxActiveBlocksPerMultiprocessor(&per_sm, lstm_persist, 256, SMEM_TOT);
    if (per_sm < 1) per_sm = 1;
    if (per_sm > 2) per_sm = 2;
    const int ncta = nsm * per_sm;

    prolog_k<<<2048, 256>>>(x, Wih0, Whh0, Wih1, Whh1, bih0, bhh0, bih1, bhh1);
    lstm_persist<<<ncta, 256, SMEM_TOT>>>(ncta);
    finalize_k<<<B_DIM, 128>>>(Wdec, bdec, out);
}

// round 11
// speedup vs baseline: 1.1521x; 1.1521x over previous
#include <cuda_runtime.h>
#include <cuda_fp16.h>
#include <cstdint>

#define B_DIM 512
#define T_DIM 128
#define D_DIM 300
#define DPAD  320
#define H_DIM 1024
#define NCOL  4096

typedef uint32_t u32;

// ------------------------------------------------------------------
// Persistent device buffers
// ------------------------------------------------------------------
__device__ __align__(16) __half g_x[(size_t)B_DIM * T_DIM * DPAD];
__device__ __align__(16) __half g_wih0[(size_t)4 * H_DIM * DPAD];
__device__ __align__(16) __half g_whh0[(size_t)4 * H_DIM * H_DIM];
__device__ __align__(16) __half g_wih1[(size_t)4 * H_DIM * H_DIM];
__device__ __align__(16) __half g_whh1[(size_t)4 * H_DIM * H_DIM];
__device__ __align__(16) __half g_h0b[2][(size_t)B_DIM * H_DIM];
__device__ __align__(16) __half g_h1b[2][(size_t)B_DIM * H_DIM];
__device__ __align__(16) float g_part[2][(size_t)B_DIM * NCOL];
__device__ __align__(16) float g_c0[(size_t)B_DIM * H_DIM];
__device__ __align__(16) float g_c1[(size_t)B_DIM * H_DIM];
__device__ __align__(16) float g_acc[(size_t)B_DIM * H_DIM];
__device__ __align__(16) float g_b0[NCOL];   // interleaved: g_b0[n] = b[(n&3)*H + (n>>2)]
__device__ __align__(16) float g_b1[NCOL];

// ------------------------------------------------------------------
// Helpers
// ------------------------------------------------------------------
__device__ __forceinline__ u32 smem_to_u32(const void* p) {
    u32 a;
    asm("{ .reg .u64 t; cvta.to.shared.u64 t, %1; cvt.u32.u64 %0, t; }" : "=r"(a) : "l"(p));
    return a;
}
__device__ __forceinline__ void cp16(u32 s, const void* g) {
    asm volatile("cp.async.cg.shared.global [%0], [%1], 16;" :: "r"(s), "l"(g));
}
__device__ __forceinline__ void mbar_init(u32 mb, u32 cnt) {
    asm volatile("mbarrier.init.shared.b64 [%0], %1;" :: "r"(mb), "r"(cnt) : "memory");
}
__device__ __forceinline__ void mbar_arrive(u32 mb) {
    asm volatile("mbarrier.arrive.shared.b64 _, [%0];" :: "r"(mb) : "memory");
}
__device__ __forceinline__ void cp_arrive_noinc(u32 mb) {
    asm volatile("cp.async.mbarrier.arrive.noinc.shared.b64 [%0];" :: "r"(mb) : "memory");
}
__device__ __forceinline__ void mbar_wait(u32 mb, u32 parity) {
    u32 done;
    asm volatile("{\n\t.reg .pred p;\n\t"
        "mbarrier.try_wait.parity.acquire.cta.shared::cta.b64 p, [%1], %2;\n\t"
        "selp.b32 %0, 1, 0, p;\n\t}" : "=r"(done) : "r"(mb), "r"(parity) : "memory");
    if (!done) {
        asm volatile("{\n\t.reg .pred P1;\n\t"
            "WAIT_LOOP_%=:\n\t"
            "mbarrier.try_wait.parity.acquire.cta.shared::cta.b64 P1, [%0], %1, 0x989680;\n\t"
            "@P1 bra.uni WAIT_DONE_%=;\n\t"
            "bra.uni WAIT_LOOP_%=;\n\t"
            "WAIT_DONE_%=:\n\t}" :: "r"(mb), "r"(parity) : "memory");
    }
}
__device__ __forceinline__ void ldsm4(u32 addr, u32* r) {
    asm volatile("ldmatrix.sync.aligned.m8n8.x4.shared.b16 {%0,%1,%2,%3}, [%4];"
                 : "=r"(r[0]), "=r"(r[1]), "=r"(r[2]), "=r"(r[3]) : "r"(addr));
}
__device__ __forceinline__ void mma_f16(float* d, const u32* a, u32 b0, u32 b1) {
    asm volatile("mma.sync.aligned.m16n8k16.row.col.f32.f16.f16.f32 "
                 "{%0,%1,%2,%3}, {%4,%5,%6,%7}, {%8,%9}, {%0,%1,%2,%3};"
                 : "+f"(d[0]), "+f"(d[1]), "+f"(d[2]), "+f"(d[3])
                 : "r"(a[0]), "r"(a[1]), "r"(a[2]), "r"(a[3]), "r"(b0), "r"(b1));
}
__device__ __forceinline__ u32 swz(u32 row, u32 q) {
    return row * 128u + ((q ^ (row & 7u)) << 4);
}
__device__ __forceinline__ float sigf(float x) { return __fdividef(1.0f, 1.0f + __expf(-x)); }
__device__ __forceinline__ float tanhf_(float x) {
    return 1.0f - 2.0f * __fdividef(1.0f, 1.0f + __expf(2.0f * x));
}

#define TILE_A_B 8192            // 64 x 64 fp16
#define TILE_W_B 16384           // 128 x 64 fp16
#define BUF_B    (TILE_A_B + TILE_W_B)    // 24576
#define SMEM_TOT (1024 + 3 * BUF_B)       // 74752 -> 3 CTAs/SM

// ------------------------------------------------------------------
// Fused GEMM + LSTM-cell step kernel (one job = one 64x128 tile).
// CTA: 256 thr, 8 warps (2M x 4N), warp tile 32x32, BK=64.
// Jobs per type: 256 (32 u-tiles x 8 m-tiles of 64 batches).
// type 0 = L1B (h1@Whh1 + part -> cell1), 1 = L1A (h0@Wih1 -> part),
// type 2 = L0 (x@Wih0 + h0@Whh0 -> cell0).
// ------------------------------------------------------------------
__global__ void __launch_bounds__(256, 3)
lstm_step(int s_l0, int s_l1b, int s_l1a) {
    extern __shared__ __align__(16) char smem[];
    const u32 sbase = smem_to_u32(smem);
    const u32 sb = sbase + 1024;
    const int tid = threadIdx.x;
    const int lane = tid & 31;
    const int wid = tid >> 5;
    const int wm = wid >> 2;          // 0..1 -> 32 rows
    const int wn = wid & 3;           // 0..3 -> 32 cols

    // job decode: groups of 256 blocks, order L0, L1B, L1A
    const int g = blockIdx.x >> 8;
    const int jb = blockIdx.x & 255;
    int type = 2, step = 0;
    {
        int k = 0;
        if (s_l0 >= 0)  { if (g == k) { type = 2; step = s_l0; }  k++; }
        if (s_l1b >= 0) { if (g == k) { type = 0; step = s_l1b; } k++; }
        if (s_l1a >= 0) { if (g == k) { type = 1; step = s_l1a; } k++; }
    }
    const int u0 = (jb & 31) * 32;    // unit tile (32 units = 128 cols)
    const int m0 = (jb >> 5) * 64;    // batch tile (64 rows)

    if (tid == 0) {
#pragma unroll
        for (int s = 0; s < 3; s++) {
            mbar_init(sbase + 32 + s * 8, 256);  // full
            mbar_init(sbase + 64 + s * 8, 256);  // empty
        }
    }
    __syncthreads();

    // loader rows: A rows 64 (tid>>2, 2 chunks), W rows 128 (tid>>1, 4 chunks)
    const int ra = tid >> 2;
    const int qa = (tid & 3) * 2;
    const int rw = tid >> 1;
    const int qw = (tid & 1) * 4;
    const int wrow = (rw & 3) * H_DIM + u0 + (rw >> 2);

    const __half *pa0, *pw0, *pa1 = nullptr, *pw1 = nullptr;
    int nc0, NC;
    if (type == 2) {
        pa0 = g_x + (size_t)(m0 + ra) * (T_DIM * DPAD) + (size_t)step * DPAD;
        pw0 = g_wih0 + (size_t)wrow * DPAD;
        nc0 = DPAD / 64;  // 5
        pa1 = g_h0b[(step - 1) & 1] + (size_t)(m0 + ra) * H_DIM;
        pw1 = g_whh0 + (size_t)wrow * H_DIM;
        NC = nc0 + 16;    // 21
    } else if (type == 1) {
        pa0 = g_h0b[step & 1] + (size_t)(m0 + ra) * H_DIM;
        pw0 = g_wih1 + (size_t)wrow * H_DIM;
        nc0 = 16; NC = 16;
    } else {
        pa0 = g_h1b[(step - 1) & 1] + (size_t)(m0 + ra) * H_DIM;
        pw0 = g_whh1 + (size_t)wrow * H_DIM;
        nc0 = 16; NC = 16;
    }

    float acc[2][4][4];
#pragma unroll
    for (int mi = 0; mi < 2; mi++)
#pragma unroll
        for (int nf = 0; nf < 4; nf++)
#pragma unroll
            for (int q = 0; q < 4; q++) acc[mi][nf][q] = 0.0f;

    auto produce = [&](int c) {
        const __half* pa; const __half* pw; int k0;
        if (c < nc0) { pa = pa0; pw = pw0; k0 = c * 64; }
        else         { pa = pa1; pw = pw1; k0 = (c - nc0) * 64; }
        const u32 d = sb + (u32)(c % 3) * BUF_B;
        cp16(d + swz((u32)ra, (u32)qa),     pa + k0 + qa * 8);
        cp16(d + swz((u32)ra, (u32)qa + 1), pa + k0 + (qa + 1) * 8);
        const u32 dw = d + TILE_A_B;
#pragma unroll
        for (int jj = 0; jj < 4; jj++) {
            const int q = qw + jj;
            cp16(dw + swz((u32)rw, (u32)q), pw + k0 + q * 8);
        }
        cp_arrive_noinc(sbase + 32 + (u32)(c % 3) * 8);
    };

    produce(0);
    produce(1);

    for (int c = 0; c < NC; c++) {
        const int pc = c + 2;
        if (pc < NC) {
            if (pc >= 3)
                mbar_wait(sbase + 64 + (u32)(pc % 3) * 8, (u32)(((pc / 3) - 1) & 1));
            produce(pc);
        }
        mbar_wait(sbase + 32 + (u32)(c % 3) * 8, (u32)((c / 3) & 1));

        const u32 bA = sb + (u32)(c % 3) * BUF_B;
        const u32 bW = bA + TILE_A_B;
#pragma unroll
        for (int kk = 0; kk < 4; kk++) {
            u32 av[2][4], wv[2][4];
            const u32 aq = 2 * kk + (lane >> 4);
#pragma unroll
            for (int mi = 0; mi < 2; mi++) {
                const u32 row = wm * 32 + mi * 16 + (lane & 15);
                ldsm4(bA + swz(row, aq), av[mi]);
            }
            const u32 wq = 2 * kk + ((lane >> 3) & 1);
#pragma unroll
            for (int nf2 = 0; nf2 < 2; nf2++) {
                const u32 row = wn * 32 + nf2 * 16 + (lane & 7) + ((lane >> 4) << 3);
                ldsm4(bW + swz(row, wq), wv[nf2]);
            }
#pragma unroll
            for (int mi = 0; mi < 2; mi++)
#pragma unroll
                for (int nf = 0; nf < 4; nf++) {
                    const u32* W = wv[nf >> 1] + (nf & 1) * 2;
                    mma_f16(acc[mi][nf], av[mi], W[0], W[1]);
                }
        }
        mbar_arrive(sbase + 64 + (u32)(c % 3) * 8);
    }

    // ---------------- epilogues ----------------
    if (type == 1) {
        float* outp = g_part[step & 1];
#pragma unroll
        for (int mi = 0; mi < 2; mi++)
#pragma unroll
            for (int nf = 0; nf < 4; nf++) {
                const int row0 = m0 + wm * 32 + mi * 16 + (lane >> 2);
                const int col = u0 * 4 + wn * 32 + nf * 8 + 2 * (lane & 3);
                *(float2*)(outp + (size_t)row0 * NCOL + col) =
                    make_float2(acc[mi][nf][0], acc[mi][nf][1]);
                *(float2*)(outp + (size_t)(row0 + 8) * NCOL + col) =
                    make_float2(acc[mi][nf][2], acc[mi][nf][3]);
            }
        return;
    }

    float* cmem = (type == 0) ? g_c1 : g_c0;
    __half* hout = (type == 0) ? g_h1b[step & 1] : g_h0b[step & 1];
    const float* extra = (type == 0) ? g_part[step & 1] : nullptr;
    const float* gb = (type == 0) ? g_b1 : g_b0;
    const bool owner = ((lane & 1) == 0);
    const int cc = 2 * (lane & 3);

#pragma unroll
    for (int mi = 0; mi < 2; mi++)
#pragma unroll
        for (int nf = 0; nf < 4; nf++) {
            float v0 = acc[mi][nf][0], v1 = acc[mi][nf][1];
            float v2 = acc[mi][nf][2], v3 = acc[mi][nf][3];
            const float p0 = __shfl_xor_sync(0xffffffffu, v0, 1);
            const float p1 = __shfl_xor_sync(0xffffffffu, v1, 1);
            const float p2 = __shfl_xor_sync(0xffffffffu, v2, 1);
            const float p3 = __shfl_xor_sync(0xffffffffu, v3, 1);
            if (owner) {
                const int nl = wn * 32 + nf * 8 + cc;
                const int ucol = u0 + (nl >> 2);
                const float4 bv = *(const float4*)(gb + u0 * 4 + nl);
                const int rowa = m0 + wm * 32 + mi * 16 + (lane >> 2);
#pragma unroll
                for (int rh = 0; rh < 2; rh++) {
                    const int b = rowa + rh * 8;
                    float iv = (rh ? v2 : v0) + bv.x;
                    float fv = (rh ? v3 : v1) + bv.y;
                    float gv = (rh ? p2 : p0) + bv.z;
                    float ov = (rh ? p3 : p1) + bv.w;
                    if (extra) {
                        const float2 e01 = *(const float2*)(extra + (size_t)b * NCOL + u0 * 4 + nl);
                        const float2 e23 = *(const float2*)(extra + (size_t)b * NCOL + u0 * 4 + nl + 2);
                        iv += e01.x; fv += e01.y; gv += e23.x; ov += e23.y;
                    }
                    const size_t ci = (size_t)b * H_DIM + ucol;
                    const float cold = cmem[ci];
                    const float cn = sigf(fv) * cold + sigf(iv) * tanhf_(gv);
                    const float hn = sigf(ov) * tanhf_(cn);
                    cmem[ci] = cn;
                    hout[ci] = __float2half(hn);
                    if (type == 0) g_acc[ci] += hn;
                }
            }
        }
}

// ------------------------------------------------------------------
__global__ void prolog_k(const float* __restrict__ x,
                         const float* __restrict__ Wih0, const float* __restrict__ Whh0,
                         const float* __restrict__ Wih1, const float* __restrict__ Whh1,
                         const float* __restrict__ bih0, const float* __restrict__ bhh0,
                         const float* __restrict__ bih1, const float* __restrict__ bhh1) {
    const size_t stride = (size_t)gridDim.x * blockDim.x;
    const size_t tid0 = (size_t)blockIdx.x * blockDim.x + threadIdx.x;
    // interleaved bias: g_b[n] = b[(n&3)*H + (n>>2)]
    for (size_t i = tid0; i < NCOL; i += stride) {
        const size_t src = (i & 3) * H_DIM + (i >> 2);
        g_b0[i] = bih0[src] + bhh0[src];
        g_b1[i] = bih1[src] + bhh1[src];
    }
    {
        const size_t n = (size_t)4 * H_DIM * DPAD;
        for (size_t i = tid0; i < n; i += stride) {
            const size_t row = i / DPAD;
            const int k = (int)(i % DPAD);
            g_wih0[i] = __float2half((k < D_DIM) ? Wih0[row * D_DIM + k] : 0.0f);
        }
    }
    {
        const size_t n = (size_t)4 * H_DIM * H_DIM;
        for (size_t i = tid0; i < n; i += stride) {
            g_whh0[i] = __float2half(Whh0[i]);
            g_wih1[i] = __float2half(Wih1[i]);
            g_whh1[i] = __float2half(Whh1[i]);
        }
    }
    {
        const size_t n = (size_t)B_DIM * T_DIM * DPAD;
        for (size_t i = tid0; i < n; i += stride) {
            const size_t bt = i / DPAD;
            const int k = (int)(i % DPAD);
            g_x[i] = __float2half((k < D_DIM) ? x[bt * D_DIM + k] : 0.0f);
        }
    }
    {
        const size_t n = (size_t)B_DIM * H_DIM;
        for (size_t i = tid0; i < n; i += stride) {
            g_h0b[0][i] = __float2half(0.0f);
            g_h0b[1][i] = __float2half(0.0f);
            g_h1b[0][i] = __float2half(0.0f);
            g_h1b[1][i] = __float2half(0.0f);
            g_c0[i] = 0.0f; g_c1[i] = 0.0f; g_acc[i] = 0.0f;
        }
    }
}

__global__ void finalize_k(const float* __restrict__ Wdec,
                           const float* __restrict__ bdec, float* __restrict__ out) {
    const int b = blockIdx.x;
    const int tid = threadIdx.x;  // 128
    float p = 0.0f;
    for (int u = tid; u < H_DIM; u += 128)
        p += g_acc[(size_t)b * H_DIM + u] * Wdec[u];
#pragma unroll
    for (int o = 16; o; o >>= 1) p += __shfl_down_sync(0xffffffffu, p, o);
    __shared__ float red[4];
    if ((tid & 31) == 0) red[tid >> 5] = p;
    __syncthreads();
    if (tid == 0)
        out[b] = (red[0] + red[1] + red[2] + red[3]) * (1.0f / (float)T_DIM) + bdec[0];
}

// ------------------------------------------------------------------
extern "C" void kernel_launch(void* const* d_in, const int* in_sizes, int n_in,
                              void* d_out, int out_size) {
    const float* x    = (const float*)d_in[0];
    const float* Wih0 = (const float*)d_in[1];
    const float* Whh0 = (const float*)d_in[2];
    const float* bih0 = (const float*)d_in[3];
    const float* bhh0 = (const float*)d_in[4];
    const float* Wih1 = (const float*)d_in[5];
    const float* Whh1 = (const float*)d_in[6];
    const float* bih1 = (const float*)d_in[7];
    const float* bhh1 = (const float*)d_in[8];
    const float* Wdec = (const float*)d_in[9];
    const float* bdec = (const float*)d_in[10];
    float* out = (float*)d_out;

    cudaFuncSetAttribute(lstm_step, cudaFuncAttributeMaxDynamicSharedMemorySize, SMEM_TOT);

    prolog_k<<<2048, 256>>>(x, Wih0, Whh0, Wih1, Whh1, bih0, bhh0, bih1, bhh1);

    // schedule: launch(t) = { L0[t+1], L1B[t-1], L1A[t] }, 256 jobs per type
    lstm_step<<<256, 256, SMEM_TOT>>>(0, -1, -1);          // L0[0]
    lstm_step<<<512, 256, SMEM_TOT>>>(1, -1, 0);           // L0[1], L1A[0]
    for (int t = 1; t <= T_DIM - 2; ++t)                   // t = 1..126
        lstm_step<<<768, 256, SMEM_TOT>>>(t + 1, t - 1, t);
    lstm_step<<<512, 256, SMEM_TOT>>>(-1, T_DIM - 2, T_DIM - 1);
    lstm_step<<<256, 256, SMEM_TOT>>>(-1, T_DIM - 1, -1);

    finalize_k<<<B_DIM, 128>>>(Wdec, bdec, out);
}